// round 9
// baseline (speedup 1.0000x reference)
#include <cuda_runtime.h>
#include <math.h>

#define NB 256
#define NN 128
#define DD 564
#define LATOFF 46
#define LATD 512
#define ROWS_TOT (NB*NN)        // 32768
#define LOSS_BLOCKS (ROWS_TOT/8) // 4096
#define CLIPV 18.420680743952367f  /* -log(1e-8) */

// ---------------- scratch (__device__ globals; no allocation allowed) ----------------
__device__ float  g_cost[NB*NN*NN];      // 16.8 MB cost matrices
__device__ float  g_lse [ROWS_TOT];      // pred logsumexp over 31 classes
__device__ float  g_nrmp[ROWS_TOT];      // pred scaled quadratic norm
__device__ float  g_nrmt[ROWS_TOT];      // target scaled quadratic norm
__device__ int    g_cls [ROWS_TOT];      // target argmax class
__device__ int    g_rows[ROWS_TOT];      // assignment: pred row per target col
__device__ double g_part[LOSS_BLOCKS*7]; // per-block loss partials

// ---------------- helpers ----------------
// small-dim mapping: 0-8 -> dims 31..39 (bmax,bmin,tr), 9-11 -> 43..45 (sc), 12-17 -> 558..563 (rot)
__device__ __forceinline__ int sdim(int l){
    if (l < 9)  return 31 + l;
    if (l < 12) return 43 + (l - 9);
    return 558 + (l - 12);
}
__device__ __forceinline__ float swgt(int l){ return (l < 12) ? (1.f/3.f) : (1.f/6.f); }

// K index (0..543) -> feature dim + sqrt(weight) scale for the folded GEMM
__device__ __forceinline__ void kmapf(int k, int& d, float& sc){
    if (k < 512){ d = LATOFF + k; sc = 0.044194173824159216f; } // 1/sqrt(512)
    else {
        int l = k - 512;
        if (l < 18){ d = sdim(l); sc = (l < 12) ? 0.5773502691896258f : 0.4082482904638631f; }
        else { d = -1; sc = 0.f; }
    }
}

// order-preserving float <-> uint for unsigned min reduction
__device__ __forceinline__ unsigned fkey(float f){
    unsigned b = __float_as_uint(f);
    return (b & 0x80000000u) ? ~b : (b | 0x80000000u);
}
__device__ __forceinline__ float unfkey(unsigned k){
    unsigned b = (k & 0x80000000u) ? (k & 0x7FFFFFFFu) : ~k;
    return __uint_as_float(b);
}

// ---------------- kernel 1: per-row stats (lse, norms, argmax class) ----------------
__global__ void rowstats_kernel(const float* __restrict__ pred, const float* __restrict__ target){
    int tid  = threadIdx.x;
    int lane = tid & 31;
    int id   = blockIdx.x * 8 + (tid >> 5);   // 0..65535 (warp per row)
    int which = id >> 15;                     // 0 = pred, 1 = target
    int r     = id & 32767;
    const float* ptr = (which ? target : pred) + (size_t)r * DD;

    // max / argmax over 31 classes (first index wins on ties)
    float v  = (lane < 31) ? ptr[lane] : -3.402823466e38f;
    int   ix = (lane < 31) ? lane : 31;
    #pragma unroll
    for (int o = 16; o; o >>= 1){
        float ov = __shfl_xor_sync(0xffffffffu, v, o);
        int   oi = __shfl_xor_sync(0xffffffffu, ix, o);
        if (ov > v || (ov == v && oi < ix)){ v = ov; ix = oi; }
    }
    // logsumexp
    float e = (lane < 31) ? expf(ptr[lane] - v) : 0.f;
    #pragma unroll
    for (int o = 16; o; o >>= 1) e += __shfl_xor_sync(0xffffffffu, e, o);
    float lse = v + logf(e);

    // scaled quadratic norm: sum lat^2/512 + sum_small w*x^2
    float acc = 0.f;
    #pragma unroll
    for (int itr = 0; itr < 16; itr++){
        float x = ptr[LATOFF + itr*32 + lane];
        acc += x * x;
    }
    acc *= (1.f/512.f);
    if (lane < 18){ float x = ptr[sdim(lane)]; acc += x * x * swgt(lane); }
    #pragma unroll
    for (int o = 16; o; o >>= 1) acc += __shfl_xor_sync(0xffffffffu, acc, o);

    if (lane == 0){
        if (which == 0){ g_lse[r] = lse; g_nrmp[r] = acc; }
        else           { g_cls[r] = ix;  g_nrmt[r] = acc; }
    }
}

// ---------------- kernel 2: cost matrices (folded GEMM, K=544) ----------------
__global__ void cost_kernel(const float* __restrict__ pred, const float* __restrict__ target){
    const int b  = blockIdx.z;
    const int it = blockIdx.y;   // pred tile (0..1)
    const int jt = blockIdx.x;   // target tile (0..1)

    __shared__ float As[32][65];    // [k][row]
    __shared__ float Bs[32][65];
    __shared__ float csA[64][32];   // pred class logits (31 + pad)
    __shared__ float lseA[64], nA[64], nB[64];
    __shared__ int   cB[64];

    int tid  = threadIdx.x;          // 256 threads
    int tx   = tid & 15, ty = tid >> 4;
    int lane = tid & 31, grp = tid >> 5;

    const float* pbase = pred   + (size_t)(b*NN + it*64) * DD;
    const float* tbase = target + (size_t)(b*NN + jt*64) * DD;

    float acc[4][4] = {};

    for (int kc = 0; kc < 17; kc++){
        int k = kc*32 + lane;
        int d; float sc;
        kmapf(k, d, sc);
        #pragma unroll
        for (int rr = 0; rr < 8; rr++){
            int row = grp + rr*8;
            As[lane][row] = (d >= 0) ? pbase[(size_t)row*DD + d] * sc : 0.f;
            Bs[lane][row] = (d >= 0) ? tbase[(size_t)row*DD + d] * sc : 0.f;
        }
        __syncthreads();
        #pragma unroll
        for (int kk = 0; kk < 32; kk++){
            float a0 = As[kk][ty*4+0], a1 = As[kk][ty*4+1], a2 = As[kk][ty*4+2], a3 = As[kk][ty*4+3];
            float b0 = Bs[kk][tx*4+0], b1 = Bs[kk][tx*4+1], b2 = Bs[kk][tx*4+2], b3 = Bs[kk][tx*4+3];
            acc[0][0] += a0*b0; acc[0][1] += a0*b1; acc[0][2] += a0*b2; acc[0][3] += a0*b3;
            acc[1][0] += a1*b0; acc[1][1] += a1*b1; acc[1][2] += a1*b2; acc[1][3] += a1*b3;
            acc[2][0] += a2*b0; acc[2][1] += a2*b1; acc[2][2] += a2*b2; acc[2][3] += a2*b3;
            acc[3][0] += a3*b0; acc[3][1] += a3*b1; acc[3][2] += a3*b2; acc[3][3] += a3*b3;
        }
        __syncthreads();
    }

    // epilogue staging
    for (int idx = tid; idx < 64*31; idx += 256){
        int r = idx / 31, c = idx % 31;
        csA[r][c] = pbase[(size_t)r*DD + c];
    }
    if (tid < 64){
        int gi = b*NN + it*64 + tid;
        int gj = b*NN + jt*64 + tid;
        lseA[tid] = g_lse[gi];  nA[tid] = g_nrmp[gi];
        nB[tid]   = g_nrmt[gj]; cB[tid] = g_cls[gj];
    }
    __syncthreads();

    #pragma unroll
    for (int a = 0; a < 4; a++){
        int il = ty*4 + a;
        float l = lseA[il], na = nA[il];
        #pragma unroll
        for (int bb = 0; bb < 4; bb++){
            int jl = tx*4 + bb;
            float ce  = fminf(l - csA[il][cB[jl]], CLIPV);
            float cst = ce + na + nB[jl] - 2.f * acc[a][bb];
            g_cost[((size_t)b*NN + it*64 + il)*NN + jt*64 + jl] = cst;
        }
    }
}

// ---------------- kernel 3: Jonker-Volgenant LSA, one block per batch ----------------
// One barrier per Dijkstra step: packed 64-bit (value,index) min with
// parity-double-buffered per-warp slots.
__global__ void lsa_kernel(){
    extern __shared__ float cs[];   // 128*128 cost, 64 KB
    __shared__ float u[NN+1];
    __shared__ int   p[NN+1];
    __shared__ int   way[NN+1];
    __shared__ unsigned long long wmin64[2][4];

    const int t = threadIdx.x;      // 128 threads; thread t owns column t+1
    const int b = blockIdx.x;

    // stage cost matrix into smem (vectorized)
    const float4* src = (const float4*)(g_cost + (size_t)b * NN * NN);
    float4* dst = (float4*)cs;
    for (int idx = t; idx < NN*NN/4; idx += NN) dst[idx] = src[idx];
    u[t] = 0.f; p[t] = 0; way[t] = 0;
    if (t == 0){ u[NN] = 0.f; p[NN] = 0; way[NN] = 0; }
    __syncthreads();

    float v = 0.f;
    const int myj  = t + 1;
    const int lane = t & 31;
    const int wrp  = t >> 5;

    for (int i = 1; i <= NN; i++){
        if (t == 0) p[0] = i;
        float minv = __int_as_float(0x7f800000);  // +inf
        bool used = false;
        int j0 = 0;
        __syncthreads();   // publishes p[0]=i, previous augment, and u updates

        for (int step = 0; step < 2*NN; step++){
            if (myj == j0) used = true;
            int   i0  = p[j0];
            float ui0 = u[i0];
            unsigned key;
            if (!used){
                float cur = cs[(i0-1)*NN + t] - ui0 - v;
                if (cur < minv){ minv = cur; way[myj] = j0; }
                key = fkey(minv);
            } else {
                key = 0xFFFFFFFFu;
            }
            // warp argmin: value via REDUX, lowest-index tie-break via ballot/ffs
            unsigned wm   = __reduce_min_sync(0xFFFFFFFFu, key);
            unsigned ball = __ballot_sync(0xFFFFFFFFu, key == wm);
            int jwarp = (wrp << 5) + (__ffs(ball) - 1) + 1;   // column index of warp argmin
            if (lane == 0)
                wmin64[step & 1][wrp] = ((unsigned long long)wm << 32) | (unsigned)jwarp;
            __syncthreads();
            const unsigned long long* s = wmin64[step & 1];
            unsigned long long g = min(min(s[0], s[1]), min(s[2], s[3]));
            int   j1    = (int)(g & 0xFFFFFFFFull);
            float delta = unfkey((unsigned)(g >> 32));

            if (used){ u[p[myj]] += delta; v -= delta; }  // distinct rows -> no conflicts
            else     { minv -= delta; }
            if (t == 0) u[i] += delta;                    // column 0 (p[0] = i)

            j0 = j1;
            if (p[j0] == 0) break;   // p[] stable inside inner loop; uniform decision
        }
        // augment along alternating path (thread 0); way[] writes were pre-barrier
        if (t == 0){
            int jj = j0;
            while (jj){ int jn = way[jj]; p[jj] = p[jn]; jj = jn; }
        }
    }
    __syncthreads();
    g_rows[b*NN + t] = p[t+1] - 1;
}

// ---------------- kernel 4: matched loss partials (warp per (b,j)) ----------------
__global__ void loss_kernel(const float* __restrict__ pred, const float* __restrict__ target){
    __shared__ float small_s[8][18];
    __shared__ float wsum[8][7];

    int tid = threadIdx.x, w = tid >> 5, lane = tid & 31;
    int id = blockIdx.x * 8 + w;          // 0..32767
    int b = id >> 7, j = id & 127;
    int i = g_rows[b*NN + j];
    const float* pp = pred   + ((size_t)b*NN + i) * DD;
    const float* tt = target + ((size_t)b*NN + j) * DD;

    // latent MSE (mean over 512)
    float la = 0.f;
    #pragma unroll
    for (int itr = 0; itr < 16; itr++){
        int d = LATOFF + itr*32 + lane;
        float df = pp[d] - tt[d];
        la += df * df;
    }
    #pragma unroll
    for (int o = 16; o; o >>= 1) la += __shfl_xor_sync(0xffffffffu, la, o);
    la *= (1.f/512.f);

    if (lane < 18){
        int d = sdim(lane);
        float df = pp[d] - tt[d];
        small_s[w][lane] = df * df;
    }
    __syncwarp();

    if (lane == 0){
        const float* s = small_s[w];
        float bmax = (s[0]+s[1]+s[2]) * (1.f/3.f);
        float bmin = (s[3]+s[4]+s[5]) * (1.f/3.f);
        float tr   = (s[6]+s[7]+s[8]) * (1.f/3.f);
        float sc   = (s[9]+s[10]+s[11]) * (1.f/3.f);
        float rot  = (s[12]+s[13]+s[14]+s[15]+s[16]+s[17]) * (1.f/6.f);
        int c = g_cls[b*NN + j];
        float ce = g_lse[b*NN + i] - pp[c];   // -log_softmax at gt class
        wsum[w][0] = ce;  wsum[w][1] = bmax; wsum[w][2] = bmin;
        wsum[w][3] = tr;  wsum[w][4] = rot;  wsum[w][5] = sc;  wsum[w][6] = la;
    }
    __syncthreads();
    if (tid == 0){
        #pragma unroll
        for (int c = 0; c < 7; c++){
            double s = 0.0;
            #pragma unroll
            for (int ww = 0; ww < 8; ww++) s += (double)wsum[ww][c];
            g_part[(size_t)blockIdx.x*7 + c] = s;
        }
    }
}

// ---------------- kernel 5: deterministic final reduction ----------------
__global__ void reduce_kernel(float* __restrict__ out, int out_size){
    __shared__ double comp[7];
    int tid = threadIdx.x, w = tid >> 5, lane = tid & 31;
    if (w < 7){
        double s = 0.0;
        int base = lane * (LOSS_BLOCKS/32);   // 128 partials per lane, fixed order
        for (int m = 0; m < LOSS_BLOCKS/32; m++) s += g_part[(size_t)(base + m)*7 + w];
        #pragma unroll
        for (int o = 16; o; o >>= 1) s += __shfl_xor_sync(0xffffffffu, s, o);
        if (lane == 0) comp[w] = s;
    }
    __syncthreads();
    if (tid == 0){
        double denom = (double)ROWS_TOT + 1e-8;
        double tot = 0.0;
        for (int c = 0; c < 7; c++) tot += comp[c];
        float vals[8];
        vals[0] = (float)(tot / denom);
        for (int c = 0; c < 7; c++) vals[1+c] = (float)(comp[c] / denom);
        int nw = out_size < 8 ? out_size : 8;
        for (int k = 0; k < nw; k++) out[k] = vals[k];
    }
    for (int k = 8 + tid; k < out_size; k += blockDim.x) out[k] = 0.f;
}

// ---------------- launch ----------------
extern "C" void kernel_launch(void* const* d_in, const int* in_sizes, int n_in,
                              void* d_out, int out_size){
    const float* pred   = (const float*)d_in[0];
    const float* target = (const float*)d_in[1];
    float* out = (float*)d_out;

    cudaFuncSetAttribute(lsa_kernel, cudaFuncAttributeMaxDynamicSharedMemorySize, NN*NN*(int)sizeof(float));

    rowstats_kernel<<<(2*ROWS_TOT)/8, 256>>>(pred, target);   // 8192 blocks, warp per row
    dim3 gc(2, 2, NB);
    cost_kernel<<<gc, 256>>>(pred, target);
    lsa_kernel<<<NB, NN, NN*NN*(int)sizeof(float)>>>();
    loss_kernel<<<LOSS_BLOCKS, 256>>>(pred, target);
    reduce_kernel<<<1, 256>>>(out, out_size);
}